// round 14
// baseline (speedup 1.0000x reference)
#include <cuda_runtime.h>
#include <cuda_bf16.h>

#define N_NODES 50000
#define N_EDGES 800000
#define DIM 128
#define NBLK 49   // ceil(50000 / 1024) for the scan kernels

// ---- device scratch (no allocations allowed) ----
__device__ __align__(16) float g_mean[(size_t)N_NODES * DIM];
__device__ __align__(16) float g_h[(size_t)N_NODES * DIM];
__device__ __align__(16) float g_y2[(size_t)N_NODES * 64];   // h @ W2l
__device__ __align__(16) float g_r2[(size_t)N_NODES * 64];   // h @ W2r
__device__ __align__(16) float g_my2[(size_t)N_NODES * 64];  // mean-agg of y2
__device__ __align__(16) int g_cnt[N_NODES + 16];
__device__ __align__(16) int g_rowptr[N_NODES + 16];
__device__ int g_cur[N_NODES];
__device__ int g_bsum[NBLK + 1];
__device__ int g_col[N_EDGES];
__device__ int g_is64;
// transposed weights, [phase][n][k], bf16 hi/lo split
__device__ __align__(16) __nv_bfloat16 g_w1h[2 * 128 * 128];
__device__ __align__(16) __nv_bfloat16 g_w1l[2 * 128 * 128];
__device__ __align__(16) __nv_bfloat16 g_w2h[2 * 64 * 128];
__device__ __align__(16) __nv_bfloat16 g_w2l[2 * 64 * 128];

__device__ __forceinline__ unsigned pack2(float a, float b) {
    unsigned short ua = __bfloat16_as_ushort(__float2bfloat16(a));
    unsigned short ub = __bfloat16_as_ushort(__float2bfloat16(b));
    return (unsigned)ua | ((unsigned)ub << 16);
}

// mma.sync m16n8k16 row.col bf16 -> f32 (sm_80+, plain-target legal)
__device__ __forceinline__ void mma16816(float& c0, float& c1, float& c2, float& c3,
                                         unsigned a0, unsigned a1, unsigned a2, unsigned a3,
                                         unsigned b0, unsigned b1) {
    asm volatile("mma.sync.aligned.m16n8k16.row.col.f32.bf16.bf16.f32 "
                 "{%0,%1,%2,%3}, {%4,%5,%6,%7}, {%8,%9}, {%0,%1,%2,%3};"
                 : "+f"(c0), "+f"(c1), "+f"(c2), "+f"(c3)
                 : "r"(a0), "r"(a1), "r"(a2), "r"(a3), "r"(b0), "r"(b1));
}

// ---------------- prep: probe + zero + weight split, one kernel ------------
__global__ void k_prep(const int* __restrict__ ei32,
                       const float* __restrict__ w1_l, const float* __restrict__ w1_r,
                       const float* __restrict__ w2_l, const float* __restrict__ w2_r,
                       __nv_bfloat16* __restrict__ w1h, __nv_bfloat16* __restrict__ w1l,
                       __nv_bfloat16* __restrict__ w2h, __nv_bfloat16* __restrict__ w2l,
                       int* __restrict__ cnt, int* __restrict__ cur,
                       int* __restrict__ is64) {
    int tid = threadIdx.x;
    int i = blockIdx.x * blockDim.x + tid;
    // dtype probe: int64 ids < 50000 -> all odd 32-bit words zero
    if (blockIdx.x == 0 && tid < 32) {
        int bad = 0;
#pragma unroll
        for (int j = 0; j < 4; ++j)
            bad |= ei32[2 * (tid * 4 + j) + 1];
        bad = __any_sync(0xffffffffu, bad != 0);
        if (tid == 0) *is64 = !bad;
    }
    if (i < N_NODES) { cnt[i] = 0; cur[i] = 0; }
    const int L1 = 2 * 128 * 128;
    const int L2 = 2 * 64 * 128;
    if (i < L1) {
        int phase = i / (128 * 128), rem = i % (128 * 128);
        int n = rem / 128, k = rem % 128;
        const float* src = phase ? w1_r : w1_l;
        float v = src[k * 128 + n];
        __nv_bfloat16 h = __float2bfloat16(v);
        w1h[i] = h;
        w1l[i] = __float2bfloat16(v - __bfloat162float(h));
    }
    if (i < L2) {
        int phase = i / (64 * 128), rem = i % (64 * 128);
        int n = rem / 128, k = rem % 128;
        const float* src = phase ? w2_r : w2_l;
        float v = src[k * 64 + n];
        __nv_bfloat16 h = __float2bfloat16(v);
        w2h[i] = h;
        w2l[i] = __float2bfloat16(v - __bfloat162float(h));
    }
}

// ---------------- CSR build (2 edges/thread, vector loads) -----------------
__global__ void k_hist(const void* __restrict__ ei, int* __restrict__ cnt,
                       const int* __restrict__ is64p) {
    int i2 = (blockIdx.x * blockDim.x + threadIdx.x) * 2;
    if (i2 >= N_EDGES) return;
    int is64 = *is64p;
    int d0, d1;
    if (is64) {
        longlong2 v = *(const longlong2*)((const long long*)ei + N_EDGES + i2);
        d0 = (int)v.x; d1 = (int)v.y;
    } else {
        int2 v = *(const int2*)((const int*)ei + N_EDGES + i2);
        d0 = v.x; d1 = v.y;
    }
    if ((unsigned)d0 < N_NODES) atomicAdd(cnt + d0, 1);
    if (i2 + 1 < N_EDGES && (unsigned)d1 < N_NODES) atomicAdd(cnt + d1, 1);
}

__global__ void k_bsum(const int* __restrict__ cnt, int* __restrict__ bsum) {
    int tid = threadIdx.x;
    int base = blockIdx.x * 1024 + tid * 4;
    int s = 0;
    if (base + 4 <= N_NODES) {
        int4 v = *(const int4*)(cnt + base);
        s = v.x + v.y + v.z + v.w;
    } else {
        for (int j = 0; j < 4; ++j)
            if (base + j < N_NODES) s += cnt[base + j];
    }
#pragma unroll
    for (int o = 16; o; o >>= 1) s += __shfl_down_sync(0xffffffffu, s, o);
    __shared__ int ws[8];
    if ((tid & 31) == 0) ws[tid >> 5] = s;
    __syncthreads();
    if (tid == 0) {
        int t = 0;
#pragma unroll
        for (int w = 0; w < 8; ++w) t += ws[w];
        bsum[blockIdx.x] = t;
    }
}

__global__ void k_bscan(int* __restrict__ bsum) {
    int tid = threadIdx.x;
    __shared__ int sh[64];
    sh[tid] = (tid < NBLK) ? bsum[tid] : 0;
    __syncthreads();
    for (int o = 1; o < 64; o <<= 1) {
        int t = (tid >= o) ? sh[tid - o] : 0;
        __syncthreads();
        sh[tid] += t;
        __syncthreads();
    }
    if (tid < NBLK) bsum[tid] = tid ? sh[tid - 1] : 0;
    if (tid == 0) bsum[NBLK] = sh[63];
}

__global__ void k_scatter(const int* __restrict__ cnt,
                          const int* __restrict__ bsum,
                          int* __restrict__ rowptr) {
    int tid = threadIdx.x;
    int lane = tid & 31, wid = tid >> 5;
    int base = blockIdx.x * 1024 + tid * 4;
    int c0 = 0, c1 = 0, c2 = 0, c3 = 0;
    if (base + 4 <= N_NODES) {
        int4 v = *(const int4*)(cnt + base);
        c0 = v.x; c1 = v.y; c2 = v.z; c3 = v.w;
    } else {
        if (base + 0 < N_NODES) c0 = cnt[base + 0];
        if (base + 1 < N_NODES) c1 = cnt[base + 1];
        if (base + 2 < N_NODES) c2 = cnt[base + 2];
        if (base + 3 < N_NODES) c3 = cnt[base + 3];
    }
    int t = c0 + c1 + c2 + c3;
    int inc = t;
#pragma unroll
    for (int o = 1; o < 32; o <<= 1) {
        int u = __shfl_up_sync(0xffffffffu, inc, o);
        if (lane >= o) inc += u;
    }
    __shared__ int wsum[8], woff[8];
    if (lane == 31) wsum[wid] = inc;
    __syncthreads();
    if (tid == 0) {
        int a = 0;
#pragma unroll
        for (int w = 0; w < 8; ++w) { woff[w] = a; a += wsum[w]; }
    }
    __syncthreads();
    int ex = bsum[blockIdx.x] + woff[wid] + (inc - t);
    int r0 = ex, r1 = ex + c0, r2 = r1 + c1, r3 = r2 + c2;
    if (base + 4 <= N_NODES) {
        *(int4*)(rowptr + base) = make_int4(r0, r1, r2, r3);
    } else {
        if (base + 0 < N_NODES) rowptr[base + 0] = r0;
        if (base + 1 < N_NODES) rowptr[base + 1] = r1;
        if (base + 2 < N_NODES) rowptr[base + 2] = r2;
        if (base + 3 < N_NODES) rowptr[base + 3] = r3;
    }
    if (blockIdx.x == NBLK - 1 && tid == 255) rowptr[N_NODES] = r3 + c3;
}

__global__ void k_fill(const void* __restrict__ ei,
                       const int* __restrict__ rowptr,
                       int* __restrict__ cur,
                       int* __restrict__ col,
                       const int* __restrict__ is64p) {
    int i2 = (blockIdx.x * blockDim.x + threadIdx.x) * 2;
    if (i2 >= N_EDGES) return;
    int is64 = *is64p;
    int s0, s1, d0, d1;
    if (is64) {
        longlong2 sv = *(const longlong2*)((const long long*)ei + i2);
        longlong2 dv = *(const longlong2*)((const long long*)ei + N_EDGES + i2);
        s0 = (int)sv.x; s1 = (int)sv.y; d0 = (int)dv.x; d1 = (int)dv.y;
    } else {
        int2 sv = *(const int2*)((const int*)ei + i2);
        int2 dv = *(const int2*)((const int*)ei + N_EDGES + i2);
        s0 = sv.x; s1 = sv.y; d0 = dv.x; d1 = dv.y;
    }
    if ((unsigned)d0 < N_NODES && (unsigned)s0 < N_NODES) {
        int pos = rowptr[d0] + atomicAdd(cur + d0, 1);
        col[pos] = s0;
    }
    if (i2 + 1 < N_EDGES && (unsigned)d1 < N_NODES && (unsigned)s1 < N_NODES) {
        int pos = rowptr[d1] + atomicAdd(cur + d1, 1);
        col[pos] = s1;
    }
}

// ---------------- mean aggregation, 128-dim: warp per node -----------------
__global__ void k_agg(const float* __restrict__ xin,
                      const int* __restrict__ rowptr,
                      const int* __restrict__ col,
                      float* __restrict__ mean) {
    int node = (blockIdx.x * blockDim.x + threadIdx.x) >> 5;
    if (node >= N_NODES) return;
    int lane = threadIdx.x & 31;
    int beg = rowptr[node], end = rowptr[node + 1];

    float4 acc = make_float4(0.f, 0.f, 0.f, 0.f);
    int e = beg;
    for (; e + 4 <= end; e += 4) {
        int s0 = col[e + 0];
        int s1 = col[e + 1];
        int s2 = col[e + 2];
        int s3 = col[e + 3];
        float4 v0 = ((const float4*)(xin + (size_t)s0 * DIM))[lane];
        float4 v1 = ((const float4*)(xin + (size_t)s1 * DIM))[lane];
        float4 v2 = ((const float4*)(xin + (size_t)s2 * DIM))[lane];
        float4 v3 = ((const float4*)(xin + (size_t)s3 * DIM))[lane];
        acc.x += v0.x + v1.x + v2.x + v3.x;
        acc.y += v0.y + v1.y + v2.y + v3.y;
        acc.z += v0.z + v1.z + v2.z + v3.z;
        acc.w += v0.w + v1.w + v2.w + v3.w;
    }
    for (; e < end; ++e) {
        int s = col[e];
        float4 v = ((const float4*)(xin + (size_t)s * DIM))[lane];
        acc.x += v.x; acc.y += v.y; acc.z += v.z; acc.w += v.w;
    }
    float inv = 1.0f / (float)max(end - beg, 1);
    acc.x *= inv; acc.y *= inv; acc.z *= inv; acc.w *= inv;
    ((float4*)(mean + (size_t)node * DIM))[lane] = acc;
}

// ---------------- mean aggregation, 64-dim: 16 lanes per node --------------
__global__ void k_agg64(const float* __restrict__ yin,
                        const int* __restrict__ rowptr,
                        const int* __restrict__ col,
                        float* __restrict__ mean) {
    int node = (blockIdx.x * blockDim.x + threadIdx.x) >> 4;
    if (node >= N_NODES) return;
    int l16 = threadIdx.x & 15;
    int beg = rowptr[node], end = rowptr[node + 1];

    float4 acc = make_float4(0.f, 0.f, 0.f, 0.f);
    int e = beg;
    for (; e + 4 <= end; e += 4) {
        int s0 = col[e + 0];
        int s1 = col[e + 1];
        int s2 = col[e + 2];
        int s3 = col[e + 3];
        float4 v0 = ((const float4*)(yin + (size_t)s0 * 64))[l16];
        float4 v1 = ((const float4*)(yin + (size_t)s1 * 64))[l16];
        float4 v2 = ((const float4*)(yin + (size_t)s2 * 64))[l16];
        float4 v3 = ((const float4*)(yin + (size_t)s3 * 64))[l16];
        acc.x += v0.x + v1.x + v2.x + v3.x;
        acc.y += v0.y + v1.y + v2.y + v3.y;
        acc.z += v0.z + v1.z + v2.z + v3.z;
        acc.w += v0.w + v1.w + v2.w + v3.w;
    }
    for (; e < end; ++e) {
        int s = col[e];
        float4 v = ((const float4*)(yin + (size_t)s * 64))[l16];
        acc.x += v.x; acc.y += v.y; acc.z += v.z; acc.w += v.w;
    }
    float inv = 1.0f / (float)max(end - beg, 1);
    acc.x *= inv; acc.y *= inv; acc.z *= inv; acc.w *= inv;
    ((float4*)(mean + (size_t)node * 64))[l16] = acc;
}

// ============ layer-1 HMMA fused GEMM + bias + row L2-normalize ============
// out = normalize( mean@Wl + Xin@Wr + bias ), DOUT=128
template <int DOUT>
__global__ void __launch_bounds__(256)
k_mgemm(const float* __restrict__ Amean,
        const float* __restrict__ Xin,
        const __nv_bfloat16* __restrict__ Wh,
        const __nv_bfloat16* __restrict__ Wlo,
        const float* __restrict__ bias,
        float* __restrict__ out) {
    constexpr int PAD = 136;
    constexpr int NT = DOUT / 8;
    constexpr int A_BYTES = 128 * PAD * 2;
    constexpr int B_BYTES = DOUT * PAD * 2;
    constexpr int OFF_AH = 0;
    constexpr int OFF_AL = A_BYTES;
    constexpr int OFF_BH = 2 * A_BYTES;
    constexpr int OFF_BL = 2 * A_BYTES + B_BYTES;
    constexpr int OFF_BIAS = 2 * A_BYTES + 2 * B_BYTES;

    extern __shared__ __align__(16) char smem[];
    unsigned* aH = (unsigned*)(smem + OFF_AH);
    unsigned* aL = (unsigned*)(smem + OFF_AL);
    unsigned* bH = (unsigned*)(smem + OFF_BH);
    unsigned* bL = (unsigned*)(smem + OFF_BL);
    float* biasS = (float*)(smem + OFF_BIAS);

    int tid = threadIdx.x;
    int wid = tid >> 5, lane = tid & 31;
    int gid = lane >> 2, q = lane & 3;
    int m0 = blockIdx.x * 128;
    int mrow = wid * 16 + gid;

    if (tid < DOUT) biasS[tid] = bias[tid];

    float acc[NT][4];
#pragma unroll
    for (int t = 0; t < NT; ++t)
#pragma unroll
        for (int j = 0; j < 4; ++j) acc[t][j] = 0.f;

#pragma unroll
    for (int phase = 0; phase < 2; ++phase) {
        const float* A = phase ? Xin : Amean;
        const __nv_bfloat16* WhP = Wh + (size_t)phase * DOUT * 128;
        const __nv_bfloat16* WlP = Wlo + (size_t)phase * DOUT * 128;
        {
            int row = tid >> 1, k0 = (tid & 1) * 64;
            int m = m0 + row;
            const float4* src = (const float4*)(A + (size_t)m * DIM + k0);
            bool ok = (m < N_NODES);
#pragma unroll
            for (int j = 0; j < 16; ++j) {
                float4 v = ok ? src[j] : make_float4(0.f, 0.f, 0.f, 0.f);
                int w = row * 68 + (k0 >> 1) + j * 2;
                aH[w] = pack2(v.x, v.y); aH[w + 1] = pack2(v.z, v.w);
                float lx = v.x - __bfloat162float(__float2bfloat16(v.x));
                float ly = v.y - __bfloat162float(__float2bfloat16(v.y));
                float lz = v.z - __bfloat162float(__float2bfloat16(v.z));
                float lw = v.w - __bfloat162float(__float2bfloat16(v.w));
                aL[w] = pack2(lx, ly); aL[w + 1] = pack2(lz, lw);
            }
        }
        if ((tid >> 1) < DOUT) {
            int r = tid >> 1, k0 = (tid & 1) * 64;
            const uint4* sh = (const uint4*)(WhP + (size_t)r * 128 + k0);
            const uint4* sl = (const uint4*)(WlP + (size_t)r * 128 + k0);
#pragma unroll
            for (int j = 0; j < 8; ++j) {
                int w = r * 68 + (k0 >> 1) + j * 4;
                *(uint4*)(bH + w) = sh[j];
                *(uint4*)(bL + w) = sl[j];
            }
        }
        __syncthreads();

#pragma unroll
        for (int k = 0; k < 128; k += 16) {
            int kw = k >> 1;
            unsigned ah0 = aH[(mrow)     * 68 + kw + q];
            unsigned ah1 = aH[(mrow + 8) * 68 + kw + q];
            unsigned ah2 = aH[(mrow)     * 68 + kw + 4 + q];
            unsigned ah3 = aH[(mrow + 8) * 68 + kw + 4 + q];
            unsigned al0 = aL[(mrow)     * 68 + kw + q];
            unsigned al1 = aL[(mrow + 8) * 68 + kw + q];
            unsigned al2 = aL[(mrow)     * 68 + kw + 4 + q];
            unsigned al3 = aL[(mrow + 8) * 68 + kw + 4 + q];
#pragma unroll
            for (int t = 0; t < NT; ++t) {
                int br = t * 8 + gid;
                unsigned bh0 = bH[br * 68 + kw + q];
                unsigned bh1 = bH[br * 68 + kw + 4 + q];
                unsigned bl0 = bL[br * 68 + kw + q];
                unsigned bl1 = bL[br * 68 + kw + 4 + q];
                mma16816(acc[t][0], acc[t][1], acc[t][2], acc[t][3],
                         ah0, ah1, ah2, ah3, bh0, bh1);
                mma16816(acc[t][0], acc[t][1], acc[t][2], acc[t][3],
                         ah0, ah1, ah2, ah3, bl0, bl1);
                mma16816(acc[t][0], acc[t][1], acc[t][2], acc[t][3],
                         al0, al1, al2, al3, bh0, bh1);
            }
        }
        __syncthreads();
    }

    float ss0 = 0.f, ss1 = 0.f;
#pragma unroll
    for (int t = 0; t < NT; ++t) {
        float b0 = biasS[t * 8 + q * 2], b1 = biasS[t * 8 + q * 2 + 1];
        acc[t][0] += b0; acc[t][1] += b1;
        acc[t][2] += b0; acc[t][3] += b1;
        ss0 += acc[t][0] * acc[t][0] + acc[t][1] * acc[t][1];
        ss1 += acc[t][2] * acc[t][2] + acc[t][3] * acc[t][3];
    }
    ss0 += __shfl_xor_sync(0xffffffffu, ss0, 1);
    ss0 += __shfl_xor_sync(0xffffffffu, ss0, 2);
    ss1 += __shfl_xor_sync(0xffffffffu, ss1, 1);
    ss1 += __shfl_xor_sync(0xffffffffu, ss1, 2);
    float sc0 = 1.0f / fmaxf(sqrtf(ss0), 1e-12f);
    float sc1 = 1.0f / fmaxf(sqrtf(ss1), 1e-12f);

    int mA = m0 + mrow, mB = mA + 8;
#pragma unroll
    for (int t = 0; t < NT; ++t) {
        int c = t * 8 + q * 2;
        if (mA < N_NODES)
            *(float2*)(out + (size_t)mA * DOUT + c) =
                make_float2(acc[t][0] * sc0, acc[t][1] * sc0);
        if (mB < N_NODES)
            *(float2*)(out + (size_t)mB * DOUT + c) =
                make_float2(acc[t][2] * sc1, acc[t][3] * sc1);
    }
}

// ============ layer-2 dual GEMM: Y2 = h@W2l, R2 = h@W2r (no bias/norm) =====
__global__ void __launch_bounds__(256)
k_dgemm64(const float* __restrict__ H,
          const __nv_bfloat16* __restrict__ Wh,   // [2][64][128]
          const __nv_bfloat16* __restrict__ Wlo,
          float* __restrict__ y2,
          float* __restrict__ r2) {
    constexpr int PAD = 136;
    constexpr int NT = 8;                     // 64/8 n-tiles
    constexpr int A_BYTES = 128 * PAD * 2;    // 34816
    constexpr int B_BYTES = 64 * PAD * 2;     // 17408
    extern __shared__ __align__(16) char smem[];
    unsigned* aH = (unsigned*)(smem);
    unsigned* aL = (unsigned*)(smem + A_BYTES);
    unsigned* bHl = (unsigned*)(smem + 2 * A_BYTES);
    unsigned* bLl = (unsigned*)(smem + 2 * A_BYTES + B_BYTES);
    unsigned* bHr = (unsigned*)(smem + 2 * A_BYTES + 2 * B_BYTES);
    unsigned* bLr = (unsigned*)(smem + 2 * A_BYTES + 3 * B_BYTES);

    int tid = threadIdx.x;
    int wid = tid >> 5, lane = tid & 31;
    int gid = lane >> 2, q = lane & 3;
    int m0 = blockIdx.x * 128;
    int mrow = wid * 16 + gid;

    // ---- A (h rows), hi/lo
    {
        int row = tid >> 1, k0 = (tid & 1) * 64;
        int m = m0 + row;
        const float4* src = (const float4*)(H + (size_t)m * DIM + k0);
        bool ok = (m < N_NODES);
#pragma unroll
        for (int j = 0; j < 16; ++j) {
            float4 v = ok ? src[j] : make_float4(0.f, 0.f, 0.f, 0.f);
            int w = row * 68 + (k0 >> 1) + j * 2;
            aH[w] = pack2(v.x, v.y); aH[w + 1] = pack2(v.z, v.w);
            float lx = v.x - __bfloat162float(__float2bfloat16(v.x));
            float ly = v.y - __bfloat162float(__float2bfloat16(v.y));
            float lz = v.z - __bfloat162float(__float2bfloat16(v.z));
            float lw = v.w - __bfloat162float(__float2bfloat16(v.w));
            aL[w] = pack2(lx, ly); aL[w + 1] = pack2(lz, lw);
        }
    }
    // ---- B: tid<128 -> W2l (phase 0), tid>=128 -> W2r (phase 1)
    {
        int p = tid >> 7;
        int r = (tid & 127) >> 1, k0 = (tid & 1) * 64;
        unsigned* dstH = p ? bHr : bHl;
        unsigned* dstL = p ? bLr : bLl;
        const uint4* sh = (const uint4*)(Wh + (size_t)p * 64 * 128 + (size_t)r * 128 + k0);
        const uint4* sl = (const uint4*)(Wlo + (size_t)p * 64 * 128 + (size_t)r * 128 + k0);
#pragma unroll
        for (int j = 0; j < 8; ++j) {
            int w = r * 68 + (k0 >> 1) + j * 4;
            *(uint4*)(dstH + w) = sh[j];
            *(uint4*)(dstL + w) = sl[j];
        }
    }
    __syncthreads();

    float accL[NT][4], accR[NT][4];
#pragma unroll
    for (int t = 0; t < NT; ++t)
#pragma unroll
        for (int j = 0; j < 4; ++j) { accL[t][j] = 0.f; accR[t][j] = 0.f; }

#pragma unroll
    for (int k = 0; k < 128; k += 16) {
        int kw = k >> 1;
        unsigned ah0 = aH[(mrow)     * 68 + kw + q];
        unsigned ah1 = aH[(mrow + 8) * 68 + kw + q];
        unsigned ah2 = aH[(mrow)     * 68 + kw + 4 + q];
        unsigned ah3 = aH[(mrow + 8) * 68 + kw + 4 + q];
        unsigned al0 = aL[(mrow)     * 68 + kw + q];
        unsigned al1 = aL[(mrow + 8) * 68 + kw + q];
        unsigned al2 = aL[(mrow)     * 68 + kw + 4 + q];
        unsigned al3 = aL[(mrow + 8) * 68 + kw + 4 + q];
#pragma unroll
        for (int t = 0; t < NT; ++t) {
            int br = t * 8 + gid;
            unsigned bh0 = bHl[br * 68 + kw + q];
            unsigned bh1 = bHl[br * 68 + kw + 4 + q];
            unsigned bl0 = bLl[br * 68 + kw + q];
            unsigned bl1 = bLl[br * 68 + kw + 4 + q];
            mma16816(accL[t][0], accL[t][1], accL[t][2], accL[t][3],
                     ah0, ah1, ah2, ah3, bh0, bh1);
            mma16816(accL[t][0], accL[t][1], accL[t][2], accL[t][3],
                     ah0, ah1, ah2, ah3, bl0, bl1);
            mma16816(accL[t][0], accL[t][1], accL[t][2], accL[t][3],
                     al0, al1, al2, al3, bh0, bh1);
            unsigned ch0 = bHr[br * 68 + kw + q];
            unsigned ch1 = bHr[br * 68 + kw + 4 + q];
            unsigned cl0 = bLr[br * 68 + kw + q];
            unsigned cl1 = bLr[br * 68 + kw + 4 + q];
            mma16816(accR[t][0], accR[t][1], accR[t][2], accR[t][3],
                     ah0, ah1, ah2, ah3, ch0, ch1);
            mma16816(accR[t][0], accR[t][1], accR[t][2], accR[t][3],
                     ah0, ah1, ah2, ah3, cl0, cl1);
            mma16816(accR[t][0], accR[t][1], accR[t][2], accR[t][3],
                     al0, al1, al2, al3, ch0, ch1);
        }
    }

    int mA = m0 + mrow, mB = mA + 8;
#pragma unroll
    for (int t = 0; t < NT; ++t) {
        int c = t * 8 + q * 2;
        if (mA < N_NODES) {
            *(float2*)(y2 + (size_t)mA * 64 + c) = make_float2(accL[t][0], accL[t][1]);
            *(float2*)(r2 + (size_t)mA * 64 + c) = make_float2(accR[t][0], accR[t][1]);
        }
        if (mB < N_NODES) {
            *(float2*)(y2 + (size_t)mB * 64 + c) = make_float2(accL[t][2], accL[t][3]);
            *(float2*)(r2 + (size_t)mB * 64 + c) = make_float2(accR[t][2], accR[t][3]);
        }
    }
}

// ---------------- finisher: out = normalize(meanY2 + R2 + bias) ------------
__global__ void k_fin(const float* __restrict__ my2,
                      const float* __restrict__ r2,
                      const float* __restrict__ bias,
                      float* __restrict__ out) {
    int row = blockIdx.x * 8 + (threadIdx.x >> 5);
    if (row >= N_NODES) return;
    int lane = threadIdx.x & 31;
    float2 a = ((const float2*)(my2 + (size_t)row * 64))[lane];
    float2 r = ((const float2*)(r2 + (size_t)row * 64))[lane];
    float2 b = ((const float2*)bias)[lane];
    float vx = a.x + r.x + b.x;
    float vy = a.y + r.y + b.y;
    float ss = vx * vx + vy * vy;
    ss += __shfl_xor_sync(0xffffffffu, ss, 1);
    ss += __shfl_xor_sync(0xffffffffu, ss, 2);
    ss += __shfl_xor_sync(0xffffffffu, ss, 4);
    ss += __shfl_xor_sync(0xffffffffu, ss, 8);
    ss += __shfl_xor_sync(0xffffffffu, ss, 16);
    float sc = 1.0f / fmaxf(sqrtf(ss), 1e-12f);
    ((float2*)(out + (size_t)row * 64))[lane] = make_float2(vx * sc, vy * sc);
}

extern "C" void kernel_launch(void* const* d_in, const int* in_sizes, int n_in,
                              void* d_out, int out_size) {
    const float* x    = (const float*)d_in[0];
    const void*  ei   = d_in[1];
    const float* w1_l = (const float*)d_in[2];
    const float* b1   = (const float*)d_in[3];
    const float* w1_r = (const float*)d_in[4];
    const float* w2_l = (const float*)d_in[5];
    const float* b2   = (const float*)d_in[6];
    const float* w2_r = (const float*)d_in[7];
    float* out = (float*)d_out;

    float *mean_p = nullptr, *h_p = nullptr, *y2_p = nullptr, *r2_p = nullptr, *my2_p = nullptr;
    int *cnt_p = nullptr, *cur_p = nullptr, *rowptr_p = nullptr,
        *col_p = nullptr, *is64_p = nullptr, *bsum_p = nullptr;
    __nv_bfloat16 *w1h_p = nullptr, *w1l_p = nullptr, *w2h_p = nullptr, *w2l_p = nullptr;
    cudaGetSymbolAddress((void**)&mean_p, g_mean);
    cudaGetSymbolAddress((void**)&h_p, g_h);
    cudaGetSymbolAddress((void**)&y2_p, g_y2);
    cudaGetSymbolAddress((void**)&r2_p, g_r2);
    cudaGetSymbolAddress((void**)&my2_p, g_my2);
    cudaGetSymbolAddress((void**)&cnt_p, g_cnt);
    cudaGetSymbolAddress((void**)&cur_p, g_cur);
    cudaGetSymbolAddress((void**)&rowptr_p, g_rowptr);
    cudaGetSymbolAddress((void**)&col_p, g_col);
    cudaGetSymbolAddress((void**)&is64_p, g_is64);
    cudaGetSymbolAddress((void**)&bsum_p, g_bsum);
    cudaGetSymbolAddress((void**)&w1h_p, g_w1h);
    cudaGetSymbolAddress((void**)&w1l_p, g_w1l);
    cudaGetSymbolAddress((void**)&w2h_p, g_w2h);
    cudaGetSymbolAddress((void**)&w2l_p, g_w2l);

    const int SMEM1 = 2 * 34816 + 2 * (128 * 136 * 2) + 512;  // 139,776 B
    const int SMEMD = 2 * 34816 + 4 * (64 * 136 * 2);         // 139,264 B
    cudaFuncSetAttribute(k_mgemm<128>, cudaFuncAttributeMaxDynamicSharedMemorySize, SMEM1);
    cudaFuncSetAttribute(k_dgemm64, cudaFuncAttributeMaxDynamicSharedMemorySize, SMEMD);

    // ---- prep (probe + zero + weight split) + CSR build ----
    k_prep<<<(N_NODES + 255) / 256, 256>>>(
        (const int*)ei, w1_l, w1_r, w2_l, w2_r,
        w1h_p, w1l_p, w2h_p, w2l_p, cnt_p, cur_p, is64_p);
    k_hist<<<(N_EDGES / 2 + 255) / 256, 256>>>(ei, cnt_p, is64_p);
    k_bsum<<<NBLK, 256>>>(cnt_p, bsum_p);
    k_bscan<<<1, 64>>>(bsum_p);
    k_scatter<<<NBLK, 256>>>(cnt_p, bsum_p, rowptr_p);
    k_fill<<<(N_EDGES / 2 + 255) / 256, 256>>>(ei, rowptr_p, cur_p, col_p, is64_p);

    // ---- layer 1: mean(x) -> g_mean; h = norm(mean@w1_l + x@w1_r + b1) ----
    k_agg<<<(N_NODES * 32 + 255) / 256, 256>>>(x, rowptr_p, col_p, mean_p);
    k_mgemm<128><<<(N_NODES + 127) / 128, 256, SMEM1>>>(mean_p, x, w1h_p, w1l_p, b1, h_p);

    // ---- layer 2 (restructured): Y2 = h@w2_l, R2 = h@w2_r; agg Y2 in 64-d;
    //      out = norm(mean(Y2) + R2 + b2)
    k_dgemm64<<<(N_NODES + 127) / 128, 256, SMEMD>>>(h_p, w2h_p, w2l_p, y2_p, r2_p);
    k_agg64<<<(N_NODES * 16 + 255) / 256, 256>>>(y2_p, rowptr_p, col_p, my2_p);
    k_fin<<<(N_NODES + 7) / 8, 256>>>(my2_p, r2_p, b2, out);
}

// round 15
// speedup vs baseline: 1.0101x; 1.0101x over previous
#include <cuda_runtime.h>
#include <cuda_bf16.h>

#define N_NODES 50000
#define N_EDGES 800000
#define DIM 128
#define NBLK 49   // ceil(50000 / 1024) for the scan kernels

// ---- device scratch (no allocations allowed) ----
__device__ __align__(16) float g_mean[(size_t)N_NODES * DIM];
__device__ __align__(16) float g_h[(size_t)N_NODES * DIM];
__device__ __align__(16) float g_y2[(size_t)N_NODES * 64];   // h @ W2l
__device__ __align__(16) float g_r2[(size_t)N_NODES * 64];   // h @ W2r
__device__ __align__(16) float g_my2[(size_t)N_NODES * 64];  // mean-agg of y2
__device__ __align__(16) int g_cnt[N_NODES + 16];
__device__ __align__(16) int g_rowptr[N_NODES + 16];
__device__ int g_cur[N_NODES];
__device__ int g_bsum[NBLK + 1];
__device__ int g_col[N_EDGES];
__device__ int g_is64;
// transposed weights, [phase][n][k], bf16 hi/lo split
__device__ __align__(16) __nv_bfloat16 g_w1h[2 * 128 * 128];
__device__ __align__(16) __nv_bfloat16 g_w1l[2 * 128 * 128];
__device__ __align__(16) __nv_bfloat16 g_w2h[2 * 64 * 128];
__device__ __align__(16) __nv_bfloat16 g_w2l[2 * 64 * 128];

__device__ __forceinline__ unsigned pack2(float a, float b) {
    unsigned short ua = __bfloat16_as_ushort(__float2bfloat16(a));
    unsigned short ub = __bfloat16_as_ushort(__float2bfloat16(b));
    return (unsigned)ua | ((unsigned)ub << 16);
}

// mma.sync m16n8k16 row.col bf16 -> f32 (sm_80+, plain-target legal)
__device__ __forceinline__ void mma16816(float& c0, float& c1, float& c2, float& c3,
                                         unsigned a0, unsigned a1, unsigned a2, unsigned a3,
                                         unsigned b0, unsigned b1) {
    asm volatile("mma.sync.aligned.m16n8k16.row.col.f32.bf16.bf16.f32 "
                 "{%0,%1,%2,%3}, {%4,%5,%6,%7}, {%8,%9}, {%0,%1,%2,%3};"
                 : "+f"(c0), "+f"(c1), "+f"(c2), "+f"(c3)
                 : "r"(a0), "r"(a1), "r"(a2), "r"(a3), "r"(b0), "r"(b1));
}

// ---------------- prep: probe + zero + weight split, one kernel ------------
__global__ void k_prep(const int* __restrict__ ei32,
                       const float* __restrict__ w1_l, const float* __restrict__ w1_r,
                       const float* __restrict__ w2_l, const float* __restrict__ w2_r,
                       __nv_bfloat16* __restrict__ w1h, __nv_bfloat16* __restrict__ w1l,
                       __nv_bfloat16* __restrict__ w2h, __nv_bfloat16* __restrict__ w2l,
                       int* __restrict__ cnt, int* __restrict__ cur,
                       int* __restrict__ is64) {
    int tid = threadIdx.x;
    int i = blockIdx.x * blockDim.x + tid;
    // dtype probe: int64 ids < 50000 -> all odd 32-bit words zero
    if (blockIdx.x == 0 && tid < 32) {
        int bad = 0;
#pragma unroll
        for (int j = 0; j < 4; ++j)
            bad |= ei32[2 * (tid * 4 + j) + 1];
        bad = __any_sync(0xffffffffu, bad != 0);
        if (tid == 0) *is64 = !bad;
    }
    if (i < N_NODES) { cnt[i] = 0; cur[i] = 0; }
    const int L1 = 2 * 128 * 128;
    const int L2 = 2 * 64 * 128;
    if (i < L1) {
        int phase = i / (128 * 128), rem = i % (128 * 128);
        int n = rem / 128, k = rem % 128;
        const float* src = phase ? w1_r : w1_l;
        float v = src[k * 128 + n];
        __nv_bfloat16 h = __float2bfloat16(v);
        w1h[i] = h;
        w1l[i] = __float2bfloat16(v - __bfloat162float(h));
    }
    if (i < L2) {
        int phase = i / (64 * 128), rem = i % (64 * 128);
        int n = rem / 128, k = rem % 128;
        const float* src = phase ? w2_r : w2_l;
        float v = src[k * 64 + n];
        __nv_bfloat16 h = __float2bfloat16(v);
        w2h[i] = h;
        w2l[i] = __float2bfloat16(v - __bfloat162float(h));
    }
}

// ---------------- CSR build (2 edges/thread, vector loads) -----------------
__global__ void k_hist(const void* __restrict__ ei, int* __restrict__ cnt,
                       const int* __restrict__ is64p) {
    int i2 = (blockIdx.x * blockDim.x + threadIdx.x) * 2;
    if (i2 >= N_EDGES) return;
    int is64 = *is64p;
    int d0, d1;
    if (is64) {
        longlong2 v = *(const longlong2*)((const long long*)ei + N_EDGES + i2);
        d0 = (int)v.x; d1 = (int)v.y;
    } else {
        int2 v = *(const int2*)((const int*)ei + N_EDGES + i2);
        d0 = v.x; d1 = v.y;
    }
    if ((unsigned)d0 < N_NODES) atomicAdd(cnt + d0, 1);
    if (i2 + 1 < N_EDGES && (unsigned)d1 < N_NODES) atomicAdd(cnt + d1, 1);
}

__global__ void k_bsum(const int* __restrict__ cnt, int* __restrict__ bsum) {
    int tid = threadIdx.x;
    int base = blockIdx.x * 1024 + tid * 4;
    int s = 0;
    if (base + 4 <= N_NODES) {
        int4 v = *(const int4*)(cnt + base);
        s = v.x + v.y + v.z + v.w;
    } else {
        for (int j = 0; j < 4; ++j)
            if (base + j < N_NODES) s += cnt[base + j];
    }
#pragma unroll
    for (int o = 16; o; o >>= 1) s += __shfl_down_sync(0xffffffffu, s, o);
    __shared__ int ws[8];
    if ((tid & 31) == 0) ws[tid >> 5] = s;
    __syncthreads();
    if (tid == 0) {
        int t = 0;
#pragma unroll
        for (int w = 0; w < 8; ++w) t += ws[w];
        bsum[blockIdx.x] = t;
    }
}

__global__ void k_bscan(int* __restrict__ bsum) {
    int tid = threadIdx.x;
    __shared__ int sh[64];
    sh[tid] = (tid < NBLK) ? bsum[tid] : 0;
    __syncthreads();
    for (int o = 1; o < 64; o <<= 1) {
        int t = (tid >= o) ? sh[tid - o] : 0;
        __syncthreads();
        sh[tid] += t;
        __syncthreads();
    }
    if (tid < NBLK) bsum[tid] = tid ? sh[tid - 1] : 0;
    if (tid == 0) bsum[NBLK] = sh[63];
}

__global__ void k_scatter(const int* __restrict__ cnt,
                          const int* __restrict__ bsum,
                          int* __restrict__ rowptr) {
    int tid = threadIdx.x;
    int lane = tid & 31, wid = tid >> 5;
    int base = blockIdx.x * 1024 + tid * 4;
    int c0 = 0, c1 = 0, c2 = 0, c3 = 0;
    if (base + 4 <= N_NODES) {
        int4 v = *(const int4*)(cnt + base);
        c0 = v.x; c1 = v.y; c2 = v.z; c3 = v.w;
    } else {
        if (base + 0 < N_NODES) c0 = cnt[base + 0];
        if (base + 1 < N_NODES) c1 = cnt[base + 1];
        if (base + 2 < N_NODES) c2 = cnt[base + 2];
        if (base + 3 < N_NODES) c3 = cnt[base + 3];
    }
    int t = c0 + c1 + c2 + c3;
    int inc = t;
#pragma unroll
    for (int o = 1; o < 32; o <<= 1) {
        int u = __shfl_up_sync(0xffffffffu, inc, o);
        if (lane >= o) inc += u;
    }
    __shared__ int wsum[8], woff[8];
    if (lane == 31) wsum[wid] = inc;
    __syncthreads();
    if (tid == 0) {
        int a = 0;
#pragma unroll
        for (int w = 0; w < 8; ++w) { woff[w] = a; a += wsum[w]; }
    }
    __syncthreads();
    int ex = bsum[blockIdx.x] + woff[wid] + (inc - t);
    int r0 = ex, r1 = ex + c0, r2 = r1 + c1, r3 = r2 + c2;
    if (base + 4 <= N_NODES) {
        *(int4*)(rowptr + base) = make_int4(r0, r1, r2, r3);
    } else {
        if (base + 0 < N_NODES) rowptr[base + 0] = r0;
        if (base + 1 < N_NODES) rowptr[base + 1] = r1;
        if (base + 2 < N_NODES) rowptr[base + 2] = r2;
        if (base + 3 < N_NODES) rowptr[base + 3] = r3;
    }
    if (blockIdx.x == NBLK - 1 && tid == 255) rowptr[N_NODES] = r3 + c3;
}

__global__ void k_fill(const void* __restrict__ ei,
                       const int* __restrict__ rowptr,
                       int* __restrict__ cur,
                       int* __restrict__ col,
                       const int* __restrict__ is64p) {
    int i2 = (blockIdx.x * blockDim.x + threadIdx.x) * 2;
    if (i2 >= N_EDGES) return;
    int is64 = *is64p;
    int s0, s1, d0, d1;
    if (is64) {
        longlong2 sv = *(const longlong2*)((const long long*)ei + i2);
        longlong2 dv = *(const longlong2*)((const long long*)ei + N_EDGES + i2);
        s0 = (int)sv.x; s1 = (int)sv.y; d0 = (int)dv.x; d1 = (int)dv.y;
    } else {
        int2 sv = *(const int2*)((const int*)ei + i2);
        int2 dv = *(const int2*)((const int*)ei + N_EDGES + i2);
        s0 = sv.x; s1 = sv.y; d0 = dv.x; d1 = dv.y;
    }
    if ((unsigned)d0 < N_NODES && (unsigned)s0 < N_NODES) {
        int pos = rowptr[d0] + atomicAdd(cur + d0, 1);
        col[pos] = s0;
    }
    if (i2 + 1 < N_EDGES && (unsigned)d1 < N_NODES && (unsigned)s1 < N_NODES) {
        int pos = rowptr[d1] + atomicAdd(cur + d1, 1);
        col[pos] = s1;
    }
}

// ---------------- mean aggregation, 128-dim: warp per node -----------------
__global__ void k_agg(const float* __restrict__ xin,
                      const int* __restrict__ rowptr,
                      const int* __restrict__ col,
                      float* __restrict__ mean) {
    int node = (blockIdx.x * blockDim.x + threadIdx.x) >> 5;
    if (node >= N_NODES) return;
    int lane = threadIdx.x & 31;
    int beg = rowptr[node], end = rowptr[node + 1];

    float4 acc = make_float4(0.f, 0.f, 0.f, 0.f);
    int e = beg;
    for (; e + 4 <= end; e += 4) {
        int s0 = col[e + 0];
        int s1 = col[e + 1];
        int s2 = col[e + 2];
        int s3 = col[e + 3];
        float4 v0 = ((const float4*)(xin + (size_t)s0 * DIM))[lane];
        float4 v1 = ((const float4*)(xin + (size_t)s1 * DIM))[lane];
        float4 v2 = ((const float4*)(xin + (size_t)s2 * DIM))[lane];
        float4 v3 = ((const float4*)(xin + (size_t)s3 * DIM))[lane];
        acc.x += v0.x + v1.x + v2.x + v3.x;
        acc.y += v0.y + v1.y + v2.y + v3.y;
        acc.z += v0.z + v1.z + v2.z + v3.z;
        acc.w += v0.w + v1.w + v2.w + v3.w;
    }
    for (; e < end; ++e) {
        int s = col[e];
        float4 v = ((const float4*)(xin + (size_t)s * DIM))[lane];
        acc.x += v.x; acc.y += v.y; acc.z += v.z; acc.w += v.w;
    }
    float inv = 1.0f / (float)max(end - beg, 1);
    acc.x *= inv; acc.y *= inv; acc.z *= inv; acc.w *= inv;
    ((float4*)(mean + (size_t)node * DIM))[lane] = acc;
}

// ---------------- mean aggregation, 64-dim: 16 lanes per node --------------
__global__ void k_agg64(const float* __restrict__ yin,
                        const int* __restrict__ rowptr,
                        const int* __restrict__ col,
                        float* __restrict__ mean) {
    int node = (blockIdx.x * blockDim.x + threadIdx.x) >> 4;
    if (node >= N_NODES) return;
    int l16 = threadIdx.x & 15;
    int beg = rowptr[node], end = rowptr[node + 1];

    float4 acc = make_float4(0.f, 0.f, 0.f, 0.f);
    int e = beg;
    for (; e + 4 <= end; e += 4) {
        int s0 = col[e + 0];
        int s1 = col[e + 1];
        int s2 = col[e + 2];
        int s3 = col[e + 3];
        float4 v0 = ((const float4*)(yin + (size_t)s0 * 64))[l16];
        float4 v1 = ((const float4*)(yin + (size_t)s1 * 64))[l16];
        float4 v2 = ((const float4*)(yin + (size_t)s2 * 64))[l16];
        float4 v3 = ((const float4*)(yin + (size_t)s3 * 64))[l16];
        acc.x += v0.x + v1.x + v2.x + v3.x;
        acc.y += v0.y + v1.y + v2.y + v3.y;
        acc.z += v0.z + v1.z + v2.z + v3.z;
        acc.w += v0.w + v1.w + v2.w + v3.w;
    }
    for (; e < end; ++e) {
        int s = col[e];
        float4 v = ((const float4*)(yin + (size_t)s * 64))[l16];
        acc.x += v.x; acc.y += v.y; acc.z += v.z; acc.w += v.w;
    }
    float inv = 1.0f / (float)max(end - beg, 1);
    acc.x *= inv; acc.y *= inv; acc.z *= inv; acc.w *= inv;
    ((float4*)(mean + (size_t)node * 64))[l16] = acc;
}

// ============ layer-1 HMMA fused GEMM + bias + row L2-normalize ============
// out = normalize( mean@Wl + Xin@Wr + bias ), DOUT=128
template <int DOUT>
__global__ void __launch_bounds__(256)
k_mgemm(const float* __restrict__ Amean,
        const float* __restrict__ Xin,
        const __nv_bfloat16* __restrict__ Wh,
        const __nv_bfloat16* __restrict__ Wlo,
        const float* __restrict__ bias,
        float* __restrict__ out) {
    constexpr int PAD = 136;
    constexpr int NT = DOUT / 8;
    constexpr int A_BYTES = 128 * PAD * 2;
    constexpr int B_BYTES = DOUT * PAD * 2;
    constexpr int OFF_AH = 0;
    constexpr int OFF_AL = A_BYTES;
    constexpr int OFF_BH = 2 * A_BYTES;
    constexpr int OFF_BL = 2 * A_BYTES + B_BYTES;
    constexpr int OFF_BIAS = 2 * A_BYTES + 2 * B_BYTES;

    extern __shared__ __align__(16) char smem[];
    unsigned* aH = (unsigned*)(smem + OFF_AH);
    unsigned* aL = (unsigned*)(smem + OFF_AL);
    unsigned* bH = (unsigned*)(smem + OFF_BH);
    unsigned* bL = (unsigned*)(smem + OFF_BL);
    float* biasS = (float*)(smem + OFF_BIAS);

    int tid = threadIdx.x;
    int wid = tid >> 5, lane = tid & 31;
    int gid = lane >> 2, q = lane & 3;
    int m0 = blockIdx.x * 128;
    int mrow = wid * 16 + gid;

    if (tid < DOUT) biasS[tid] = bias[tid];

    float acc[NT][4];
#pragma unroll
    for (int t = 0; t < NT; ++t)
#pragma unroll
        for (int j = 0; j < 4; ++j) acc[t][j] = 0.f;

#pragma unroll
    for (int phase = 0; phase < 2; ++phase) {
        const float* A = phase ? Xin : Amean;
        const __nv_bfloat16* WhP = Wh + (size_t)phase * DOUT * 128;
        const __nv_bfloat16* WlP = Wlo + (size_t)phase * DOUT * 128;
        {
            int row = tid >> 1, k0 = (tid & 1) * 64;
            int m = m0 + row;
            const float4* src = (const float4*)(A + (size_t)m * DIM + k0);
            bool ok = (m < N_NODES);
#pragma unroll
            for (int j = 0; j < 16; ++j) {
                float4 v = ok ? src[j] : make_float4(0.f, 0.f, 0.f, 0.f);
                int w = row * 68 + (k0 >> 1) + j * 2;
                aH[w] = pack2(v.x, v.y); aH[w + 1] = pack2(v.z, v.w);
                float lx = v.x - __bfloat162float(__float2bfloat16(v.x));
                float ly = v.y - __bfloat162float(__float2bfloat16(v.y));
                float lz = v.z - __bfloat162float(__float2bfloat16(v.z));
                float lw = v.w - __bfloat162float(__float2bfloat16(v.w));
                aL[w] = pack2(lx, ly); aL[w + 1] = pack2(lz, lw);
            }
        }
        if ((tid >> 1) < DOUT) {
            int r = tid >> 1, k0 = (tid & 1) * 64;
            const uint4* sh = (const uint4*)(WhP + (size_t)r * 128 + k0);
            const uint4* sl = (const uint4*)(WlP + (size_t)r * 128 + k0);
#pragma unroll
            for (int j = 0; j < 8; ++j) {
                int w = r * 68 + (k0 >> 1) + j * 4;
                *(uint4*)(bH + w) = sh[j];
                *(uint4*)(bL + w) = sl[j];
            }
        }
        __syncthreads();

#pragma unroll
        for (int k = 0; k < 128; k += 16) {
            int kw = k >> 1;
            unsigned ah0 = aH[(mrow)     * 68 + kw + q];
            unsigned ah1 = aH[(mrow + 8) * 68 + kw + q];
            unsigned ah2 = aH[(mrow)     * 68 + kw + 4 + q];
            unsigned ah3 = aH[(mrow + 8) * 68 + kw + 4 + q];
            unsigned al0 = aL[(mrow)     * 68 + kw + q];
            unsigned al1 = aL[(mrow + 8) * 68 + kw + q];
            unsigned al2 = aL[(mrow)     * 68 + kw + 4 + q];
            unsigned al3 = aL[(mrow + 8) * 68 + kw + 4 + q];
#pragma unroll
            for (int t = 0; t < NT; ++t) {
                int br = t * 8 + gid;
                unsigned bh0 = bH[br * 68 + kw + q];
                unsigned bh1 = bH[br * 68 + kw + 4 + q];
                unsigned bl0 = bL[br * 68 + kw + q];
                unsigned bl1 = bL[br * 68 + kw + 4 + q];
                mma16816(acc[t][0], acc[t][1], acc[t][2], acc[t][3],
                         ah0, ah1, ah2, ah3, bh0, bh1);
                mma16816(acc[t][0], acc[t][1], acc[t][2], acc[t][3],
                         ah0, ah1, ah2, ah3, bl0, bl1);
                mma16816(acc[t][0], acc[t][1], acc[t][2], acc[t][3],
                         al0, al1, al2, al3, bh0, bh1);
            }
        }
        __syncthreads();
    }

    float ss0 = 0.f, ss1 = 0.f;
#pragma unroll
    for (int t = 0; t < NT; ++t) {
        float b0 = biasS[t * 8 + q * 2], b1 = biasS[t * 8 + q * 2 + 1];
        acc[t][0] += b0; acc[t][1] += b1;
        acc[t][2] += b0; acc[t][3] += b1;
        ss0 += acc[t][0] * acc[t][0] + acc[t][1] * acc[t][1];
        ss1 += acc[t][2] * acc[t][2] + acc[t][3] * acc[t][3];
    }
    ss0 += __shfl_xor_sync(0xffffffffu, ss0, 1);
    ss0 += __shfl_xor_sync(0xffffffffu, ss0, 2);
    ss1 += __shfl_xor_sync(0xffffffffu, ss1, 1);
    ss1 += __shfl_xor_sync(0xffffffffu, ss1, 2);
    float sc0 = 1.0f / fmaxf(sqrtf(ss0), 1e-12f);
    float sc1 = 1.0f / fmaxf(sqrtf(ss1), 1e-12f);

    int mA = m0 + mrow, mB = mA + 8;
#pragma unroll
    for (int t = 0; t < NT; ++t) {
        int c = t * 8 + q * 2;
        if (mA < N_NODES)
            *(float2*)(out + (size_t)mA * DOUT + c) =
                make_float2(acc[t][0] * sc0, acc[t][1] * sc0);
        if (mB < N_NODES)
            *(float2*)(out + (size_t)mB * DOUT + c) =
                make_float2(acc[t][2] * sc1, acc[t][3] * sc1);
    }
}

// ============ layer-2 dual GEMM: Y2 = h@W2l, R2 = h@W2r (no bias/norm) =====
__global__ void __launch_bounds__(256)
k_dgemm64(const float* __restrict__ H,
          const __nv_bfloat16* __restrict__ Wh,   // [2][64][128]
          const __nv_bfloat16* __restrict__ Wlo,
          float* __restrict__ y2,
          float* __restrict__ r2) {
    constexpr int PAD = 136;
    constexpr int NT = 8;                     // 64/8 n-tiles
    constexpr int A_BYTES = 128 * PAD * 2;    // 34816
    constexpr int B_BYTES = 64 * PAD * 2;     // 17408
    extern __shared__ __align__(16) char smem[];
    unsigned* aH = (unsigned*)(smem);
    unsigned* aL = (unsigned*)(smem + A_BYTES);
    unsigned* bHl = (unsigned*)(smem + 2 * A_BYTES);
    unsigned* bLl = (unsigned*)(smem + 2 * A_BYTES + B_BYTES);
    unsigned* bHr = (unsigned*)(smem + 2 * A_BYTES + 2 * B_BYTES);
    unsigned* bLr = (unsigned*)(smem + 2 * A_BYTES + 3 * B_BYTES);

    int tid = threadIdx.x;
    int wid = tid >> 5, lane = tid & 31;
    int gid = lane >> 2, q = lane & 3;
    int m0 = blockIdx.x * 128;
    int mrow = wid * 16 + gid;

    // ---- A (h rows), hi/lo
    {
        int row = tid >> 1, k0 = (tid & 1) * 64;
        int m = m0 + row;
        const float4* src = (const float4*)(H + (size_t)m * DIM + k0);
        bool ok = (m < N_NODES);
#pragma unroll
        for (int j = 0; j < 16; ++j) {
            float4 v = ok ? src[j] : make_float4(0.f, 0.f, 0.f, 0.f);
            int w = row * 68 + (k0 >> 1) + j * 2;
            aH[w] = pack2(v.x, v.y); aH[w + 1] = pack2(v.z, v.w);
            float lx = v.x - __bfloat162float(__float2bfloat16(v.x));
            float ly = v.y - __bfloat162float(__float2bfloat16(v.y));
            float lz = v.z - __bfloat162float(__float2bfloat16(v.z));
            float lw = v.w - __bfloat162float(__float2bfloat16(v.w));
            aL[w] = pack2(lx, ly); aL[w + 1] = pack2(lz, lw);
        }
    }
    // ---- B: tid<128 -> W2l (phase 0), tid>=128 -> W2r (phase 1)
    {
        int p = tid >> 7;
        int r = (tid & 127) >> 1, k0 = (tid & 1) * 64;
        unsigned* dstH = p ? bHr : bHl;
        unsigned* dstL = p ? bLr : bLl;
        const uint4* sh = (const uint4*)(Wh + (size_t)p * 64 * 128 + (size_t)r * 128 + k0);
        const uint4* sl = (const uint4*)(Wlo + (size_t)p * 64 * 128 + (size_t)r * 128 + k0);
#pragma unroll
        for (int j = 0; j < 8; ++j) {
            int w = r * 68 + (k0 >> 1) + j * 4;
            *(uint4*)(dstH + w) = sh[j];
            *(uint4*)(dstL + w) = sl[j];
        }
    }
    __syncthreads();

    float accL[NT][4], accR[NT][4];
#pragma unroll
    for (int t = 0; t < NT; ++t)
#pragma unroll
        for (int j = 0; j < 4; ++j) { accL[t][j] = 0.f; accR[t][j] = 0.f; }

#pragma unroll
    for (int k = 0; k < 128; k += 16) {
        int kw = k >> 1;
        unsigned ah0 = aH[(mrow)     * 68 + kw + q];
        unsigned ah1 = aH[(mrow + 8) * 68 + kw + q];
        unsigned ah2 = aH[(mrow)     * 68 + kw + 4 + q];
        unsigned ah3 = aH[(mrow + 8) * 68 + kw + 4 + q];
        unsigned al0 = aL[(mrow)     * 68 + kw + q];
        unsigned al1 = aL[(mrow + 8) * 68 + kw + q];
        unsigned al2 = aL[(mrow)     * 68 + kw + 4 + q];
        unsigned al3 = aL[(mrow + 8) * 68 + kw + 4 + q];
#pragma unroll
        for (int t = 0; t < NT; ++t) {
            int br = t * 8 + gid;
            unsigned bh0 = bHl[br * 68 + kw + q];
            unsigned bh1 = bHl[br * 68 + kw + 4 + q];
            unsigned bl0 = bLl[br * 68 + kw + q];
            unsigned bl1 = bLl[br * 68 + kw + 4 + q];
            mma16816(accL[t][0], accL[t][1], accL[t][2], accL[t][3],
                     ah0, ah1, ah2, ah3, bh0, bh1);
            mma16816(accL[t][0], accL[t][1], accL[t][2], accL[t][3],
                     ah0, ah1, ah2, ah3, bl0, bl1);
            mma16816(accL[t][0], accL[t][1], accL[t][2], accL[t][3],
                     al0, al1, al2, al3, bh0, bh1);
            unsigned ch0 = bHr[br * 68 + kw + q];
            unsigned ch1 = bHr[br * 68 + kw + 4 + q];
            unsigned cl0 = bLr[br * 68 + kw + q];
            unsigned cl1 = bLr[br * 68 + kw + 4 + q];
            mma16816(accR[t][0], accR[t][1], accR[t][2], accR[t][3],
                     ah0, ah1, ah2, ah3, ch0, ch1);
            mma16816(accR[t][0], accR[t][1], accR[t][2], accR[t][3],
                     ah0, ah1, ah2, ah3, cl0, cl1);
            mma16816(accR[t][0], accR[t][1], accR[t][2], accR[t][3],
                     al0, al1, al2, al3, ch0, ch1);
        }
    }

    int mA = m0 + mrow, mB = mA + 8;
#pragma unroll
    for (int t = 0; t < NT; ++t) {
        int c = t * 8 + q * 2;
        if (mA < N_NODES) {
            *(float2*)(y2 + (size_t)mA * 64 + c) = make_float2(accL[t][0], accL[t][1]);
            *(float2*)(r2 + (size_t)mA * 64 + c) = make_float2(accR[t][0], accR[t][1]);
        }
        if (mB < N_NODES) {
            *(float2*)(y2 + (size_t)mB * 64 + c) = make_float2(accL[t][2], accL[t][3]);
            *(float2*)(r2 + (size_t)mB * 64 + c) = make_float2(accR[t][2], accR[t][3]);
        }
    }
}

// ---------------- finisher: out = normalize(meanY2 + R2 + bias) ------------
__global__ void k_fin(const float* __restrict__ my2,
                      const float* __restrict__ r2,
                      const float* __restrict__ bias,
                      float* __restrict__ out) {
    int row = blockIdx.x * 8 + (threadIdx.x >> 5);
    if (row >= N_NODES) return;
    int lane = threadIdx.x & 31;
    float2 a = ((const float2*)(my2 + (size_t)row * 64))[lane];
    float2 r = ((const float2*)(r2 + (size_t)row * 64))[lane];
    float2 b = ((const float2*)bias)[lane];
    float vx = a.x + r.x + b.x;
    float vy = a.y + r.y + b.y;
    float ss = vx * vx + vy * vy;
    ss += __shfl_xor_sync(0xffffffffu, ss, 1);
    ss += __shfl_xor_sync(0xffffffffu, ss, 2);
    ss += __shfl_xor_sync(0xffffffffu, ss, 4);
    ss += __shfl_xor_sync(0xffffffffu, ss, 8);
    ss += __shfl_xor_sync(0xffffffffu, ss, 16);
    float sc = 1.0f / fmaxf(sqrtf(ss), 1e-12f);
    ((float2*)(out + (size_t)row * 64))[lane] = make_float2(vx * sc, vy * sc);
}

extern "C" void kernel_launch(void* const* d_in, const int* in_sizes, int n_in,
                              void* d_out, int out_size) {
    const float* x    = (const float*)d_in[0];
    const void*  ei   = d_in[1];
    const float* w1_l = (const float*)d_in[2];
    const float* b1   = (const float*)d_in[3];
    const float* w1_r = (const float*)d_in[4];
    const float* w2_l = (const float*)d_in[5];
    const float* b2   = (const float*)d_in[6];
    const float* w2_r = (const float*)d_in[7];
    float* out = (float*)d_out;

    float *mean_p = nullptr, *h_p = nullptr, *y2_p = nullptr, *r2_p = nullptr, *my2_p = nullptr;
    int *cnt_p = nullptr, *cur_p = nullptr, *rowptr_p = nullptr,
        *col_p = nullptr, *is64_p = nullptr, *bsum_p = nullptr;
    __nv_bfloat16 *w1h_p = nullptr, *w1l_p = nullptr, *w2h_p = nullptr, *w2l_p = nullptr;
    cudaGetSymbolAddress((void**)&mean_p, g_mean);
    cudaGetSymbolAddress((void**)&h_p, g_h);
    cudaGetSymbolAddress((void**)&y2_p, g_y2);
    cudaGetSymbolAddress((void**)&r2_p, g_r2);
    cudaGetSymbolAddress((void**)&my2_p, g_my2);
    cudaGetSymbolAddress((void**)&cnt_p, g_cnt);
    cudaGetSymbolAddress((void**)&cur_p, g_cur);
    cudaGetSymbolAddress((void**)&rowptr_p, g_rowptr);
    cudaGetSymbolAddress((void**)&col_p, g_col);
    cudaGetSymbolAddress((void**)&is64_p, g_is64);
    cudaGetSymbolAddress((void**)&bsum_p, g_bsum);
    cudaGetSymbolAddress((void**)&w1h_p, g_w1h);
    cudaGetSymbolAddress((void**)&w1l_p, g_w1l);
    cudaGetSymbolAddress((void**)&w2h_p, g_w2h);
    cudaGetSymbolAddress((void**)&w2l_p, g_w2l);

    const int SMEM1 = 2 * 34816 + 2 * (128 * 136 * 2) + 512;  // 139,776 B
    const int SMEMD = 2 * 34816 + 4 * (64 * 136 * 2);         // 139,264 B
    cudaFuncSetAttribute(k_mgemm<128>, cudaFuncAttributeMaxDynamicSharedMemorySize, SMEM1);
    cudaFuncSetAttribute(k_dgemm64, cudaFuncAttributeMaxDynamicSharedMemorySize, SMEMD);

    // ---- prep (probe + zero + weight split) + CSR build ----
    k_prep<<<(N_NODES + 255) / 256, 256>>>(
        (const int*)ei, w1_l, w1_r, w2_l, w2_r,
        w1h_p, w1l_p, w2h_p, w2l_p, cnt_p, cur_p, is64_p);
    k_hist<<<(N_EDGES / 2 + 255) / 256, 256>>>(ei, cnt_p, is64_p);
    k_bsum<<<NBLK, 256>>>(cnt_p, bsum_p);
    k_bscan<<<1, 64>>>(bsum_p);
    k_scatter<<<NBLK, 256>>>(cnt_p, bsum_p, rowptr_p);
    k_fill<<<(N_EDGES / 2 + 255) / 256, 256>>>(ei, rowptr_p, cur_p, col_p, is64_p);

    // ---- layer 1: mean(x) -> g_mean; h = norm(mean@w1_l + x@w1_r + b1) ----
    k_agg<<<(N_NODES * 32 + 255) / 256, 256>>>(x, rowptr_p, col_p, mean_p);
    k_mgemm<128><<<(N_NODES + 127) / 128, 256, SMEM1>>>(mean_p, x, w1h_p, w1l_p, b1, h_p);

    // ---- layer 2 (restructured): Y2 = h@w2_l, R2 = h@w2_r; agg Y2 in 64-d;
    //      out = norm(mean(Y2) + R2 + b2)
    k_dgemm64<<<(N_NODES + 127) / 128, 256, SMEMD>>>(h_p, w2h_p, w2l_p, y2_p, r2_p);
    k_agg64<<<(N_NODES * 16 + 255) / 256, 256>>>(y2_p, rowptr_p, col_p, my2_p);
    k_fin<<<(N_NODES + 7) / 8, 256>>>(my2_p, r2_p, b2, out);
}

// round 16
// speedup vs baseline: 1.0115x; 1.0015x over previous
#include <cuda_runtime.h>
#include <cuda_bf16.h>

#define N_NODES 50000
#define N_EDGES 800000
#define DIM 128
#define NBLK 49   // ceil(50000 / 1024) for the scan kernels

// ---- device scratch (no allocations allowed) ----
__device__ __align__(16) float g_mean[(size_t)N_NODES * DIM];
__device__ __align__(16) float g_h[(size_t)N_NODES * DIM];
__device__ __align__(16) float g_y2[(size_t)N_NODES * 64];   // h @ W2l
__device__ __align__(16) float g_r2[(size_t)N_NODES * 64];   // h @ W2r
__device__ __align__(16) float g_my2[(size_t)N_NODES * 64];  // mean-agg of y2
__device__ __align__(16) int g_cnt[N_NODES + 16];
__device__ __align__(16) int g_rowptr[N_NODES + 16];
__device__ int g_cur[N_NODES];
__device__ int g_bsum[NBLK + 1];
__device__ int g_col[N_EDGES];
__device__ int g_is64;
// transposed weights, [phase][n][k], bf16 hi/lo split
__device__ __align__(16) __nv_bfloat16 g_w1h[2 * 128 * 128];
__device__ __align__(16) __nv_bfloat16 g_w1l[2 * 128 * 128];
__device__ __align__(16) __nv_bfloat16 g_w2h[2 * 64 * 128];
__device__ __align__(16) __nv_bfloat16 g_w2l[2 * 64 * 128];

__device__ __forceinline__ unsigned pack2(float a, float b) {
    unsigned short ua = __bfloat16_as_ushort(__float2bfloat16(a));
    unsigned short ub = __bfloat16_as_ushort(__float2bfloat16(b));
    return (unsigned)ua | ((unsigned)ub << 16);
}

// mma.sync m16n8k16 row.col bf16 -> f32 (sm_80+, plain-target legal)
__device__ __forceinline__ void mma16816(float& c0, float& c1, float& c2, float& c3,
                                         unsigned a0, unsigned a1, unsigned a2, unsigned a3,
                                         unsigned b0, unsigned b1) {
    asm volatile("mma.sync.aligned.m16n8k16.row.col.f32.bf16.bf16.f32 "
                 "{%0,%1,%2,%3}, {%4,%5,%6,%7}, {%8,%9}, {%0,%1,%2,%3};"
                 : "+f"(c0), "+f"(c1), "+f"(c2), "+f"(c3)
                 : "r"(a0), "r"(a1), "r"(a2), "r"(a3), "r"(b0), "r"(b1));
}

// ---------------- prep: probe + zero + weight split, one kernel ------------
__global__ void k_prep(const int* __restrict__ ei32,
                       const float* __restrict__ w1_l, const float* __restrict__ w1_r,
                       const float* __restrict__ w2_l, const float* __restrict__ w2_r,
                       __nv_bfloat16* __restrict__ w1h, __nv_bfloat16* __restrict__ w1l,
                       __nv_bfloat16* __restrict__ w2h, __nv_bfloat16* __restrict__ w2l,
                       int* __restrict__ cnt, int* __restrict__ cur,
                       int* __restrict__ is64) {
    int tid = threadIdx.x;
    int i = blockIdx.x * blockDim.x + tid;
    // dtype probe: int64 ids < 50000 -> all odd 32-bit words zero
    if (blockIdx.x == 0 && tid < 32) {
        int bad = 0;
#pragma unroll
        for (int j = 0; j < 4; ++j)
            bad |= ei32[2 * (tid * 4 + j) + 1];
        bad = __any_sync(0xffffffffu, bad != 0);
        if (tid == 0) *is64 = !bad;
    }
    if (i < N_NODES) { cnt[i] = 0; cur[i] = 0; }
    const int L1 = 2 * 128 * 128;
    const int L2 = 2 * 64 * 128;
    if (i < L1) {
        int phase = i / (128 * 128), rem = i % (128 * 128);
        int n = rem / 128, k = rem % 128;
        const float* src = phase ? w1_r : w1_l;
        float v = src[k * 128 + n];
        __nv_bfloat16 h = __float2bfloat16(v);
        w1h[i] = h;
        w1l[i] = __float2bfloat16(v - __bfloat162float(h));
    }
    if (i < L2) {
        int phase = i / (64 * 128), rem = i % (64 * 128);
        int n = rem / 128, k = rem % 128;
        const float* src = phase ? w2_r : w2_l;
        float v = src[k * 64 + n];
        __nv_bfloat16 h = __float2bfloat16(v);
        w2h[i] = h;
        w2l[i] = __float2bfloat16(v - __bfloat162float(h));
    }
}

// ---------------- CSR build (2 edges/thread, vector loads) -----------------
__global__ void k_hist(const void* __restrict__ ei, int* __restrict__ cnt,
                       const int* __restrict__ is64p) {
    int i2 = (blockIdx.x * blockDim.x + threadIdx.x) * 2;
    if (i2 >= N_EDGES) return;
    int is64 = *is64p;
    int d0, d1;
    if (is64) {
        longlong2 v = *(const longlong2*)((const long long*)ei + N_EDGES + i2);
        d0 = (int)v.x; d1 = (int)v.y;
    } else {
        int2 v = *(const int2*)((const int*)ei + N_EDGES + i2);
        d0 = v.x; d1 = v.y;
    }
    if ((unsigned)d0 < N_NODES) atomicAdd(cnt + d0, 1);
    if (i2 + 1 < N_EDGES && (unsigned)d1 < N_NODES) atomicAdd(cnt + d1, 1);
}

__global__ void k_bsum(const int* __restrict__ cnt, int* __restrict__ bsum) {
    int tid = threadIdx.x;
    int base = blockIdx.x * 1024 + tid * 4;
    int s = 0;
    if (base + 4 <= N_NODES) {
        int4 v = *(const int4*)(cnt + base);
        s = v.x + v.y + v.z + v.w;
    } else {
        for (int j = 0; j < 4; ++j)
            if (base + j < N_NODES) s += cnt[base + j];
    }
#pragma unroll
    for (int o = 16; o; o >>= 1) s += __shfl_down_sync(0xffffffffu, s, o);
    __shared__ int ws[8];
    if ((tid & 31) == 0) ws[tid >> 5] = s;
    __syncthreads();
    if (tid == 0) {
        int t = 0;
#pragma unroll
        for (int w = 0; w < 8; ++w) t += ws[w];
        bsum[blockIdx.x] = t;
    }
}

__global__ void k_bscan(int* __restrict__ bsum) {
    int tid = threadIdx.x;
    __shared__ int sh[64];
    sh[tid] = (tid < NBLK) ? bsum[tid] : 0;
    __syncthreads();
    for (int o = 1; o < 64; o <<= 1) {
        int t = (tid >= o) ? sh[tid - o] : 0;
        __syncthreads();
        sh[tid] += t;
        __syncthreads();
    }
    if (tid < NBLK) bsum[tid] = tid ? sh[tid - 1] : 0;
    if (tid == 0) bsum[NBLK] = sh[63];
}

__global__ void k_scatter(const int* __restrict__ cnt,
                          const int* __restrict__ bsum,
                          int* __restrict__ rowptr) {
    int tid = threadIdx.x;
    int lane = tid & 31, wid = tid >> 5;
    int base = blockIdx.x * 1024 + tid * 4;
    int c0 = 0, c1 = 0, c2 = 0, c3 = 0;
    if (base + 4 <= N_NODES) {
        int4 v = *(const int4*)(cnt + base);
        c0 = v.x; c1 = v.y; c2 = v.z; c3 = v.w;
    } else {
        if (base + 0 < N_NODES) c0 = cnt[base + 0];
        if (base + 1 < N_NODES) c1 = cnt[base + 1];
        if (base + 2 < N_NODES) c2 = cnt[base + 2];
        if (base + 3 < N_NODES) c3 = cnt[base + 3];
    }
    int t = c0 + c1 + c2 + c3;
    int inc = t;
#pragma unroll
    for (int o = 1; o < 32; o <<= 1) {
        int u = __shfl_up_sync(0xffffffffu, inc, o);
        if (lane >= o) inc += u;
    }
    __shared__ int wsum[8], woff[8];
    if (lane == 31) wsum[wid] = inc;
    __syncthreads();
    if (tid == 0) {
        int a = 0;
#pragma unroll
        for (int w = 0; w < 8; ++w) { woff[w] = a; a += wsum[w]; }
    }
    __syncthreads();
    int ex = bsum[blockIdx.x] + woff[wid] + (inc - t);
    int r0 = ex, r1 = ex + c0, r2 = r1 + c1, r3 = r2 + c2;
    if (base + 4 <= N_NODES) {
        *(int4*)(rowptr + base) = make_int4(r0, r1, r2, r3);
    } else {
        if (base + 0 < N_NODES) rowptr[base + 0] = r0;
        if (base + 1 < N_NODES) rowptr[base + 1] = r1;
        if (base + 2 < N_NODES) rowptr[base + 2] = r2;
        if (base + 3 < N_NODES) rowptr[base + 3] = r3;
    }
    if (blockIdx.x == NBLK - 1 && tid == 255) rowptr[N_NODES] = r3 + c3;
}

__global__ void k_fill(const void* __restrict__ ei,
                       const int* __restrict__ rowptr,
                       int* __restrict__ cur,
                       int* __restrict__ col,
                       const int* __restrict__ is64p) {
    int i2 = (blockIdx.x * blockDim.x + threadIdx.x) * 2;
    if (i2 >= N_EDGES) return;
    int is64 = *is64p;
    int s0, s1, d0, d1;
    if (is64) {
        longlong2 sv = *(const longlong2*)((const long long*)ei + i2);
        longlong2 dv = *(const longlong2*)((const long long*)ei + N_EDGES + i2);
        s0 = (int)sv.x; s1 = (int)sv.y; d0 = (int)dv.x; d1 = (int)dv.y;
    } else {
        int2 sv = *(const int2*)((const int*)ei + i2);
        int2 dv = *(const int2*)((const int*)ei + N_EDGES + i2);
        s0 = sv.x; s1 = sv.y; d0 = dv.x; d1 = dv.y;
    }
    if ((unsigned)d0 < N_NODES && (unsigned)s0 < N_NODES) {
        int pos = rowptr[d0] + atomicAdd(cur + d0, 1);
        col[pos] = s0;
    }
    if (i2 + 1 < N_EDGES && (unsigned)d1 < N_NODES && (unsigned)s1 < N_NODES) {
        int pos = rowptr[d1] + atomicAdd(cur + d1, 1);
        col[pos] = s1;
    }
}

// ---------------- mean aggregation, 128-dim: warp per node -----------------
__global__ void k_agg(const float* __restrict__ xin,
                      const int* __restrict__ rowptr,
                      const int* __restrict__ col,
                      float* __restrict__ mean) {
    int node = (blockIdx.x * blockDim.x + threadIdx.x) >> 5;
    if (node >= N_NODES) return;
    int lane = threadIdx.x & 31;
    int beg = rowptr[node], end = rowptr[node + 1];

    float4 acc = make_float4(0.f, 0.f, 0.f, 0.f);
    int e = beg;
    for (; e + 4 <= end; e += 4) {
        int s0 = col[e + 0];
        int s1 = col[e + 1];
        int s2 = col[e + 2];
        int s3 = col[e + 3];
        float4 v0 = ((const float4*)(xin + (size_t)s0 * DIM))[lane];
        float4 v1 = ((const float4*)(xin + (size_t)s1 * DIM))[lane];
        float4 v2 = ((const float4*)(xin + (size_t)s2 * DIM))[lane];
        float4 v3 = ((const float4*)(xin + (size_t)s3 * DIM))[lane];
        acc.x += v0.x + v1.x + v2.x + v3.x;
        acc.y += v0.y + v1.y + v2.y + v3.y;
        acc.z += v0.z + v1.z + v2.z + v3.z;
        acc.w += v0.w + v1.w + v2.w + v3.w;
    }
    for (; e < end; ++e) {
        int s = col[e];
        float4 v = ((const float4*)(xin + (size_t)s * DIM))[lane];
        acc.x += v.x; acc.y += v.y; acc.z += v.z; acc.w += v.w;
    }
    float inv = 1.0f / (float)max(end - beg, 1);
    acc.x *= inv; acc.y *= inv; acc.z *= inv; acc.w *= inv;
    ((float4*)(mean + (size_t)node * DIM))[lane] = acc;
}

// ---------------- mean aggregation, 64-dim: 16 lanes per node --------------
__global__ void k_agg64(const float* __restrict__ yin,
                        const int* __restrict__ rowptr,
                        const int* __restrict__ col,
                        float* __restrict__ mean) {
    int node = (blockIdx.x * blockDim.x + threadIdx.x) >> 4;
    if (node >= N_NODES) return;
    int l16 = threadIdx.x & 15;
    int beg = rowptr[node], end = rowptr[node + 1];

    float4 acc = make_float4(0.f, 0.f, 0.f, 0.f);
    int e = beg;
    for (; e + 4 <= end; e += 4) {
        int s0 = col[e + 0];
        int s1 = col[e + 1];
        int s2 = col[e + 2];
        int s3 = col[e + 3];
        float4 v0 = ((const float4*)(yin + (size_t)s0 * 64))[l16];
        float4 v1 = ((const float4*)(yin + (size_t)s1 * 64))[l16];
        float4 v2 = ((const float4*)(yin + (size_t)s2 * 64))[l16];
        float4 v3 = ((const float4*)(yin + (size_t)s3 * 64))[l16];
        acc.x += v0.x + v1.x + v2.x + v3.x;
        acc.y += v0.y + v1.y + v2.y + v3.y;
        acc.z += v0.z + v1.z + v2.z + v3.z;
        acc.w += v0.w + v1.w + v2.w + v3.w;
    }
    for (; e < end; ++e) {
        int s = col[e];
        float4 v = ((const float4*)(yin + (size_t)s * 64))[l16];
        acc.x += v.x; acc.y += v.y; acc.z += v.z; acc.w += v.w;
    }
    float inv = 1.0f / (float)max(end - beg, 1);
    acc.x *= inv; acc.y *= inv; acc.z *= inv; acc.w *= inv;
    ((float4*)(mean + (size_t)node * 64))[l16] = acc;
}

// ============ layer-1 HMMA fused GEMM + bias + row L2-normalize ============
// out = normalize( mean@Wl + Xin@Wr + bias ), DOUT=128
template <int DOUT>
__global__ void __launch_bounds__(256)
k_mgemm(const float* __restrict__ Amean,
        const float* __restrict__ Xin,
        const __nv_bfloat16* __restrict__ Wh,
        const __nv_bfloat16* __restrict__ Wlo,
        const float* __restrict__ bias,
        float* __restrict__ out) {
    constexpr int PAD = 136;
    constexpr int NT = DOUT / 8;
    constexpr int A_BYTES = 128 * PAD * 2;
    constexpr int B_BYTES = DOUT * PAD * 2;
    constexpr int OFF_AH = 0;
    constexpr int OFF_AL = A_BYTES;
    constexpr int OFF_BH = 2 * A_BYTES;
    constexpr int OFF_BL = 2 * A_BYTES + B_BYTES;
    constexpr int OFF_BIAS = 2 * A_BYTES + 2 * B_BYTES;

    extern __shared__ __align__(16) char smem[];
    unsigned* aH = (unsigned*)(smem + OFF_AH);
    unsigned* aL = (unsigned*)(smem + OFF_AL);
    unsigned* bH = (unsigned*)(smem + OFF_BH);
    unsigned* bL = (unsigned*)(smem + OFF_BL);
    float* biasS = (float*)(smem + OFF_BIAS);

    int tid = threadIdx.x;
    int wid = tid >> 5, lane = tid & 31;
    int gid = lane >> 2, q = lane & 3;
    int m0 = blockIdx.x * 128;
    int mrow = wid * 16 + gid;

    if (tid < DOUT) biasS[tid] = bias[tid];

    float acc[NT][4];
#pragma unroll
    for (int t = 0; t < NT; ++t)
#pragma unroll
        for (int j = 0; j < 4; ++j) acc[t][j] = 0.f;

#pragma unroll
    for (int phase = 0; phase < 2; ++phase) {
        const float* A = phase ? Xin : Amean;
        const __nv_bfloat16* WhP = Wh + (size_t)phase * DOUT * 128;
        const __nv_bfloat16* WlP = Wlo + (size_t)phase * DOUT * 128;
        {
            int row = tid >> 1, k0 = (tid & 1) * 64;
            int m = m0 + row;
            const float4* src = (const float4*)(A + (size_t)m * DIM + k0);
            bool ok = (m < N_NODES);
#pragma unroll
            for (int j = 0; j < 16; ++j) {
                float4 v = ok ? src[j] : make_float4(0.f, 0.f, 0.f, 0.f);
                int w = row * 68 + (k0 >> 1) + j * 2;
                aH[w] = pack2(v.x, v.y); aH[w + 1] = pack2(v.z, v.w);
                float lx = v.x - __bfloat162float(__float2bfloat16(v.x));
                float ly = v.y - __bfloat162float(__float2bfloat16(v.y));
                float lz = v.z - __bfloat162float(__float2bfloat16(v.z));
                float lw = v.w - __bfloat162float(__float2bfloat16(v.w));
                aL[w] = pack2(lx, ly); aL[w + 1] = pack2(lz, lw);
            }
        }
        if ((tid >> 1) < DOUT) {
            int r = tid >> 1, k0 = (tid & 1) * 64;
            const uint4* sh = (const uint4*)(WhP + (size_t)r * 128 + k0);
            const uint4* sl = (const uint4*)(WlP + (size_t)r * 128 + k0);
#pragma unroll
            for (int j = 0; j < 8; ++j) {
                int w = r * 68 + (k0 >> 1) + j * 4;
                *(uint4*)(bH + w) = sh[j];
                *(uint4*)(bL + w) = sl[j];
            }
        }
        __syncthreads();

#pragma unroll
        for (int k = 0; k < 128; k += 16) {
            int kw = k >> 1;
            unsigned ah0 = aH[(mrow)     * 68 + kw + q];
            unsigned ah1 = aH[(mrow + 8) * 68 + kw + q];
            unsigned ah2 = aH[(mrow)     * 68 + kw + 4 + q];
            unsigned ah3 = aH[(mrow + 8) * 68 + kw + 4 + q];
            unsigned al0 = aL[(mrow)     * 68 + kw + q];
            unsigned al1 = aL[(mrow + 8) * 68 + kw + q];
            unsigned al2 = aL[(mrow)     * 68 + kw + 4 + q];
            unsigned al3 = aL[(mrow + 8) * 68 + kw + 4 + q];
#pragma unroll
            for (int t = 0; t < NT; ++t) {
                int br = t * 8 + gid;
                unsigned bh0 = bH[br * 68 + kw + q];
                unsigned bh1 = bH[br * 68 + kw + 4 + q];
                unsigned bl0 = bL[br * 68 + kw + q];
                unsigned bl1 = bL[br * 68 + kw + 4 + q];
                mma16816(acc[t][0], acc[t][1], acc[t][2], acc[t][3],
                         ah0, ah1, ah2, ah3, bh0, bh1);
                mma16816(acc[t][0], acc[t][1], acc[t][2], acc[t][3],
                         ah0, ah1, ah2, ah3, bl0, bl1);
                mma16816(acc[t][0], acc[t][1], acc[t][2], acc[t][3],
                         al0, al1, al2, al3, bh0, bh1);
            }
        }
        __syncthreads();
    }

    float ss0 = 0.f, ss1 = 0.f;
#pragma unroll
    for (int t = 0; t < NT; ++t) {
        float b0 = biasS[t * 8 + q * 2], b1 = biasS[t * 8 + q * 2 + 1];
        acc[t][0] += b0; acc[t][1] += b1;
        acc[t][2] += b0; acc[t][3] += b1;
        ss0 += acc[t][0] * acc[t][0] + acc[t][1] * acc[t][1];
        ss1 += acc[t][2] * acc[t][2] + acc[t][3] * acc[t][3];
    }
    ss0 += __shfl_xor_sync(0xffffffffu, ss0, 1);
    ss0 += __shfl_xor_sync(0xffffffffu, ss0, 2);
    ss1 += __shfl_xor_sync(0xffffffffu, ss1, 1);
    ss1 += __shfl_xor_sync(0xffffffffu, ss1, 2);
    float sc0 = 1.0f / fmaxf(sqrtf(ss0), 1e-12f);
    float sc1 = 1.0f / fmaxf(sqrtf(ss1), 1e-12f);

    int mA = m0 + mrow, mB = mA + 8;
#pragma unroll
    for (int t = 0; t < NT; ++t) {
        int c = t * 8 + q * 2;
        if (mA < N_NODES)
            *(float2*)(out + (size_t)mA * DOUT + c) =
                make_float2(acc[t][0] * sc0, acc[t][1] * sc0);
        if (mB < N_NODES)
            *(float2*)(out + (size_t)mB * DOUT + c) =
                make_float2(acc[t][2] * sc1, acc[t][3] * sc1);
    }
}

// ============ layer-2 dual GEMM: Y2 = h@W2l, R2 = h@W2r (no bias/norm) =====
__global__ void __launch_bounds__(256)
k_dgemm64(const float* __restrict__ H,
          const __nv_bfloat16* __restrict__ Wh,   // [2][64][128]
          const __nv_bfloat16* __restrict__ Wlo,
          float* __restrict__ y2,
          float* __restrict__ r2) {
    constexpr int PAD = 136;
    constexpr int NT = 8;                     // 64/8 n-tiles
    constexpr int A_BYTES = 128 * PAD * 2;    // 34816
    constexpr int B_BYTES = 64 * PAD * 2;     // 17408
    extern __shared__ __align__(16) char smem[];
    unsigned* aH = (unsigned*)(smem);
    unsigned* aL = (unsigned*)(smem + A_BYTES);
    unsigned* bHl = (unsigned*)(smem + 2 * A_BYTES);
    unsigned* bLl = (unsigned*)(smem + 2 * A_BYTES + B_BYTES);
    unsigned* bHr = (unsigned*)(smem + 2 * A_BYTES + 2 * B_BYTES);
    unsigned* bLr = (unsigned*)(smem + 2 * A_BYTES + 3 * B_BYTES);

    int tid = threadIdx.x;
    int wid = tid >> 5, lane = tid & 31;
    int gid = lane >> 2, q = lane & 3;
    int m0 = blockIdx.x * 128;
    int mrow = wid * 16 + gid;

    // ---- A (h rows), hi/lo
    {
        int row = tid >> 1, k0 = (tid & 1) * 64;
        int m = m0 + row;
        const float4* src = (const float4*)(H + (size_t)m * DIM + k0);
        bool ok = (m < N_NODES);
#pragma unroll
        for (int j = 0; j < 16; ++j) {
            float4 v = ok ? src[j] : make_float4(0.f, 0.f, 0.f, 0.f);
            int w = row * 68 + (k0 >> 1) + j * 2;
            aH[w] = pack2(v.x, v.y); aH[w + 1] = pack2(v.z, v.w);
            float lx = v.x - __bfloat162float(__float2bfloat16(v.x));
            float ly = v.y - __bfloat162float(__float2bfloat16(v.y));
            float lz = v.z - __bfloat162float(__float2bfloat16(v.z));
            float lw = v.w - __bfloat162float(__float2bfloat16(v.w));
            aL[w] = pack2(lx, ly); aL[w + 1] = pack2(lz, lw);
        }
    }
    // ---- B: tid<128 -> W2l (phase 0), tid>=128 -> W2r (phase 1)
    {
        int p = tid >> 7;
        int r = (tid & 127) >> 1, k0 = (tid & 1) * 64;
        unsigned* dstH = p ? bHr : bHl;
        unsigned* dstL = p ? bLr : bLl;
        const uint4* sh = (const uint4*)(Wh + (size_t)p * 64 * 128 + (size_t)r * 128 + k0);
        const uint4* sl = (const uint4*)(Wlo + (size_t)p * 64 * 128 + (size_t)r * 128 + k0);
#pragma unroll
        for (int j = 0; j < 8; ++j) {
            int w = r * 68 + (k0 >> 1) + j * 4;
            *(uint4*)(dstH + w) = sh[j];
            *(uint4*)(dstL + w) = sl[j];
        }
    }
    __syncthreads();

    float accL[NT][4], accR[NT][4];
#pragma unroll
    for (int t = 0; t < NT; ++t)
#pragma unroll
        for (int j = 0; j < 4; ++j) { accL[t][j] = 0.f; accR[t][j] = 0.f; }

#pragma unroll
    for (int k = 0; k < 128; k += 16) {
        int kw = k >> 1;
        unsigned ah0 = aH[(mrow)     * 68 + kw + q];
        unsigned ah1 = aH[(mrow + 8) * 68 + kw + q];
        unsigned ah2 = aH[(mrow)     * 68 + kw + 4 + q];
        unsigned ah3 = aH[(mrow + 8) * 68 + kw + 4 + q];
        unsigned al0 = aL[(mrow)     * 68 + kw + q];
        unsigned al1 = aL[(mrow + 8) * 68 + kw + q];
        unsigned al2 = aL[(mrow)     * 68 + kw + 4 + q];
        unsigned al3 = aL[(mrow + 8) * 68 + kw + 4 + q];
#pragma unroll
        for (int t = 0; t < NT; ++t) {
            int br = t * 8 + gid;
            unsigned bh0 = bHl[br * 68 + kw + q];
            unsigned bh1 = bHl[br * 68 + kw + 4 + q];
            unsigned bl0 = bLl[br * 68 + kw + q];
            unsigned bl1 = bLl[br * 68 + kw + 4 + q];
            mma16816(accL[t][0], accL[t][1], accL[t][2], accL[t][3],
                     ah0, ah1, ah2, ah3, bh0, bh1);
            mma16816(accL[t][0], accL[t][1], accL[t][2], accL[t][3],
                     ah0, ah1, ah2, ah3, bl0, bl1);
            mma16816(accL[t][0], accL[t][1], accL[t][2], accL[t][3],
                     al0, al1, al2, al3, bh0, bh1);
            unsigned ch0 = bHr[br * 68 + kw + q];
            unsigned ch1 = bHr[br * 68 + kw + 4 + q];
            unsigned cl0 = bLr[br * 68 + kw + q];
            unsigned cl1 = bLr[br * 68 + kw + 4 + q];
            mma16816(accR[t][0], accR[t][1], accR[t][2], accR[t][3],
                     ah0, ah1, ah2, ah3, ch0, ch1);
            mma16816(accR[t][0], accR[t][1], accR[t][2], accR[t][3],
                     ah0, ah1, ah2, ah3, cl0, cl1);
            mma16816(accR[t][0], accR[t][1], accR[t][2], accR[t][3],
                     al0, al1, al2, al3, ch0, ch1);
        }
    }

    int mA = m0 + mrow, mB = mA + 8;
#pragma unroll
    for (int t = 0; t < NT; ++t) {
        int c = t * 8 + q * 2;
        if (mA < N_NODES) {
            *(float2*)(y2 + (size_t)mA * 64 + c) = make_float2(accL[t][0], accL[t][1]);
            *(float2*)(r2 + (size_t)mA * 64 + c) = make_float2(accR[t][0], accR[t][1]);
        }
        if (mB < N_NODES) {
            *(float2*)(y2 + (size_t)mB * 64 + c) = make_float2(accL[t][2], accL[t][3]);
            *(float2*)(r2 + (size_t)mB * 64 + c) = make_float2(accR[t][2], accR[t][3]);
        }
    }
}

// ---------------- finisher: out = normalize(meanY2 + R2 + bias) ------------
__global__ void k_fin(const float* __restrict__ my2,
                      const float* __restrict__ r2,
                      const float* __restrict__ bias,
                      float* __restrict__ out) {
    int row = blockIdx.x * 8 + (threadIdx.x >> 5);
    if (row >= N_NODES) return;
    int lane = threadIdx.x & 31;
    float2 a = ((const float2*)(my2 + (size_t)row * 64))[lane];
    float2 r = ((const float2*)(r2 + (size_t)row * 64))[lane];
    float2 b = ((const float2*)bias)[lane];
    float vx = a.x + r.x + b.x;
    float vy = a.y + r.y + b.y;
    float ss = vx * vx + vy * vy;
    ss += __shfl_xor_sync(0xffffffffu, ss, 1);
    ss += __shfl_xor_sync(0xffffffffu, ss, 2);
    ss += __shfl_xor_sync(0xffffffffu, ss, 4);
    ss += __shfl_xor_sync(0xffffffffu, ss, 8);
    ss += __shfl_xor_sync(0xffffffffu, ss, 16);
    float sc = 1.0f / fmaxf(sqrtf(ss), 1e-12f);
    ((float2*)(out + (size_t)row * 64))[lane] = make_float2(vx * sc, vy * sc);
}

extern "C" void kernel_launch(void* const* d_in, const int* in_sizes, int n_in,
                              void* d_out, int out_size) {
    const float* x    = (const float*)d_in[0];
    const void*  ei   = d_in[1];
    const float* w1_l = (const float*)d_in[2];
    const float* b1   = (const float*)d_in[3];
    const float* w1_r = (const float*)d_in[4];
    const float* w2_l = (const float*)d_in[5];
    const float* b2   = (const float*)d_in[6];
    const float* w2_r = (const float*)d_in[7];
    float* out = (float*)d_out;

    float *mean_p = nullptr, *h_p = nullptr, *y2_p = nullptr, *r2_p = nullptr, *my2_p = nullptr;
    int *cnt_p = nullptr, *cur_p = nullptr, *rowptr_p = nullptr,
        *col_p = nullptr, *is64_p = nullptr, *bsum_p = nullptr;
    __nv_bfloat16 *w1h_p = nullptr, *w1l_p = nullptr, *w2h_p = nullptr, *w2l_p = nullptr;
    cudaGetSymbolAddress((void**)&mean_p, g_mean);
    cudaGetSymbolAddress((void**)&h_p, g_h);
    cudaGetSymbolAddress((void**)&y2_p, g_y2);
    cudaGetSymbolAddress((void**)&r2_p, g_r2);
    cudaGetSymbolAddress((void**)&my2_p, g_my2);
    cudaGetSymbolAddress((void**)&cnt_p, g_cnt);
    cudaGetSymbolAddress((void**)&cur_p, g_cur);
    cudaGetSymbolAddress((void**)&rowptr_p, g_rowptr);
    cudaGetSymbolAddress((void**)&col_p, g_col);
    cudaGetSymbolAddress((void**)&is64_p, g_is64);
    cudaGetSymbolAddress((void**)&bsum_p, g_bsum);
    cudaGetSymbolAddress((void**)&w1h_p, g_w1h);
    cudaGetSymbolAddress((void**)&w1l_p, g_w1l);
    cudaGetSymbolAddress((void**)&w2h_p, g_w2h);
    cudaGetSymbolAddress((void**)&w2l_p, g_w2l);

    const int SMEM1 = 2 * 34816 + 2 * (128 * 136 * 2) + 512;  // 139,776 B
    const int SMEMD = 2 * 34816 + 4 * (64 * 136 * 2);         // 139,264 B
    cudaFuncSetAttribute(k_mgemm<128>, cudaFuncAttributeMaxDynamicSharedMemorySize, SMEM1);
    cudaFuncSetAttribute(k_dgemm64, cudaFuncAttributeMaxDynamicSharedMemorySize, SMEMD);

    // ---- prep (probe + zero + weight split) + CSR build ----
    k_prep<<<(N_NODES + 255) / 256, 256>>>(
        (const int*)ei, w1_l, w1_r, w2_l, w2_r,
        w1h_p, w1l_p, w2h_p, w2l_p, cnt_p, cur_p, is64_p);
    k_hist<<<(N_EDGES / 2 + 255) / 256, 256>>>(ei, cnt_p, is64_p);
    k_bsum<<<NBLK, 256>>>(cnt_p, bsum_p);
    k_bscan<<<1, 64>>>(bsum_p);
    k_scatter<<<NBLK, 256>>>(cnt_p, bsum_p, rowptr_p);
    k_fill<<<(N_EDGES / 2 + 255) / 256, 256>>>(ei, rowptr_p, cur_p, col_p, is64_p);

    // ---- layer 1: mean(x) -> g_mean; h = norm(mean@w1_l + x@w1_r + b1) ----
    k_agg<<<(N_NODES * 32 + 255) / 256, 256>>>(x, rowptr_p, col_p, mean_p);
    k_mgemm<128><<<(N_NODES + 127) / 128, 256, SMEM1>>>(mean_p, x, w1h_p, w1l_p, b1, h_p);

    // ---- layer 2 (restructured): Y2 = h@w2_l, R2 = h@w2_r; agg Y2 in 64-d;
    //      out = norm(mean(Y2) + R2 + b2)
    k_dgemm64<<<(N_NODES + 127) / 128, 256, SMEMD>>>(h_p, w2h_p, w2l_p, y2_p, r2_p);
    k_agg64<<<(N_NODES * 16 + 255) / 256, 256>>>(y2_p, rowptr_p, col_p, my2_p);
    k_fin<<<(N_NODES + 7) / 8, 256>>>(my2_p, r2_p, b2, out);
}